// round 8
// baseline (speedup 1.0000x reference)
#include <cuda_runtime.h>
#include <cuda_fp16.h>
#include <cuda_bf16.h>
#include <stdint.h>

// ---------------- static scratch (no allocation allowed) ----------------
#define N_MAX 100352          // >= N=100000
#define E_MAX 1700000         // >= E=1600000
#define F 128                 // feature dim
#define SA 136                // padded smem row stride (halves)
#define TILE 1024             // scan tile size
#define MAXTILES 128

__device__ __align__(16) static __half g_t1[(size_t)N_MAX * F];  // x@W1 (fp16, unscaled)
__device__ __align__(16) static __half g_h1[(size_t)N_MAX * F];  // relu layer-1 out (fp16)
__device__ __align__(16) static __half g_t2[(size_t)N_MAX * F];  // h1@W2 (fp16, unscaled)
__device__ __align__(16) static float g_dis[N_MAX];
__device__ static int   g_degc[N_MAX];
__device__ static int   g_rowptr[N_MAX + 4];
__device__ static int   g_rank[E_MAX];
__device__ static int   g_csr[E_MAX];
__device__ static int   g_counts[1024];
__device__ static unsigned long long g_tile_state[MAXTILES];  // (flag<<32)|sum
__device__ static int   g_tile_ctr;
__device__ static int   g_e64;
__device__ static int   g_b64;

// ---------------- kernel: dtype detect + zero everything ----------------
__global__ void setup_kernel(const int* __restrict__ e, const int* __restrict__ b,
                             int nwords, float* __restrict__ out, int outw, int n) {
    if (blockIdx.x < 2) {
        __shared__ int any;
        if (threadIdx.x == 0) any = 0;
        __syncthreads();
        const int* a = (blockIdx.x == 0) ? e : b;
        int local = 0;
        for (int i = 1 + 2 * (int)threadIdx.x; i < nwords; i += 2 * (int)blockDim.x)
            local |= a[i];
        if (local) atomicOr(&any, 1);
        __syncthreads();
        if (threadIdx.x == 0) {
            int is64 = (any == 0) ? 1 : 0;
            if (blockIdx.x == 0) { g_e64 = is64; g_tile_ctr = 0; }
            else g_b64 = is64;
        }
        if (blockIdx.x == 1) {
            for (int i = threadIdx.x; i < MAXTILES; i += blockDim.x) g_tile_state[i] = 0ull;
            for (int i = threadIdx.x; i < 1024; i += blockDim.x) g_counts[i] = 0;
        }
        return;
    }
    int nb = gridDim.x - 2;
    long long idx = (long long)(blockIdx.x - 2) * blockDim.x + threadIdx.x;
    long long stride = (long long)nb * blockDim.x;
    for (long long i = idx; i < n; i += stride) g_degc[i] = 0;
    for (long long i = idx; i < outw; i += stride) out[i] = 0.f;
}

__device__ __forceinline__ long long load_idx(const void* p, long long i, int is64) {
    if (is64) return ((const long long*)p)[i];
    return (long long)((const int*)p)[i];
}

// load edge indices [2t, 2t+1] from the src half (off=0) or dst half (off=E)
__device__ __forceinline__ void load_pair(const void* p, long long base2t, int is64,
                                          int& v0, int& v1) {
    if (is64) {
        longlong2 v = ((const longlong2*)p)[base2t >> 1];
        v0 = (int)v.x; v1 = (int)v.y;
    } else {
        int2 v = ((const int2*)p)[base2t >> 1];
        v0 = v.x; v1 = v.y;
    }
}

// ---------------- degree histogram + per-edge rank (2 edges/thread) --------
__global__ void deg_kernel(const void* __restrict__ edge, int E) {
    int t = blockIdx.x * blockDim.x + threadIdx.x;
    int e0 = 2 * t;
    if (e0 >= E) return;
    int is64 = g_e64;
    int d0, d1;
    load_pair(edge, (long long)E + e0, is64, d0, d1);
    g_rank[e0] = atomicAdd(&g_degc[d0], 1);
    if (e0 + 1 < E) g_rank[e0 + 1] = atomicAdd(&g_degc[d1], 1);
}

// ---------------- single-pass scan (decoupled lookback) + dis ----------
__global__ void __launch_bounds__(TILE) scan_kernel(int n) {
    __shared__ int sh[TILE];
    __shared__ int s_bid;
    __shared__ int s_prefix;
    int t = threadIdx.x;
    if (t == 0) s_bid = atomicAdd(&g_tile_ctr, 1);
    __syncthreads();
    int bid = s_bid;
    int i = bid * TILE + t;
    int v = (i < n) ? g_degc[i] : 0;
    if (i < n) g_dis[i] = rsqrtf((float)(v + 1));     // +1 self loop
    sh[t] = v;
    __syncthreads();
    for (int off = 1; off < TILE; off <<= 1) {
        int tmp = (t >= off) ? sh[t - off] : 0;
        __syncthreads();
        sh[t] += tmp;
        __syncthreads();
    }
    int total = sh[TILE - 1];
    if (t == 0) {
        if (bid == 0) {
            atomicExch(&g_tile_state[0], (2ull << 32) | (unsigned)total);
            s_prefix = 0;
        } else {
            atomicExch(&g_tile_state[bid], (1ull << 32) | (unsigned)total);
            int prefix = 0;
            int j = bid - 1;
            while (j >= 0) {
                unsigned long long st = atomicAdd(&g_tile_state[j], 0ull);
                unsigned flag = (unsigned)(st >> 32);
                if (flag == 2u) { prefix += (int)(unsigned)st; break; }
                if (flag == 1u) { prefix += (int)(unsigned)st; j--; }
            }
            atomicExch(&g_tile_state[bid], (2ull << 32) | (unsigned)(prefix + total));
            s_prefix = prefix;
        }
    }
    __syncthreads();
    int prefix = s_prefix;
    if (i < n) {
        int r = prefix + sh[t] - v;   // global exclusive
        g_rowptr[i] = r;
        if (i == n - 1) g_rowptr[n] = r + v;
    }
}

// ---------------- CSR fill, atomic-free (2 edges/thread) ----------------
__global__ void fill_kernel(const void* __restrict__ edge, int E) {
    int t = blockIdx.x * blockDim.x + threadIdx.x;
    int e0 = 2 * t;
    if (e0 >= E) return;
    int is64 = g_e64;
    int s0, s1, d0, d1;
    load_pair(edge, (long long)e0, is64, s0, s1);
    load_pair(edge, (long long)E + e0, is64, d0, d1);
    int2 rk = *(const int2*)&g_rank[e0];
    g_csr[g_rowptr[d0] + rk.x] = s0;
    if (e0 + 1 < E) g_csr[g_rowptr[d1] + rk.y] = s1;
}

// ---------------- tensor-core GEMM: C = fp16(A @ W), unscaled ----------------
template<bool A_IS_HALF>
__global__ void __launch_bounds__(256) gemm_mma_kernel(
    const void* __restrict__ Aptr, const float* __restrict__ W,
    __half* __restrict__ C, int n)
{
    extern __shared__ __half sh[];
    __half* As = sh;                 // [128][SA]
    __half* Wt = sh + 128 * SA;      // [128][SA] transposed

    int t = threadIdx.x;
    int row0 = blockIdx.x * 128;

    for (int i = t; i < F * F; i += 256) {
        int k = i >> 7, nn = i & 127;
        Wt[nn * SA + k] = __float2half(__ldg(&W[i]));
    }

    if (A_IS_HALF) {
        const __half* A = (const __half*)Aptr;
        for (int i = t; i < 128 * F / 8; i += 256) {
            int lin = i * 8;
            int r = lin >> 7, c = lin & 127;
            uint4 v = make_uint4(0u, 0u, 0u, 0u);
            if (row0 + r < n) v = *(const uint4*)&A[(size_t)(row0 + r) * F + c];
            *(uint4*)&As[r * SA + c] = v;
        }
    } else {
        const float* A = (const float*)Aptr;
        for (int i = t; i < 128 * F / 4; i += 256) {
            int lin = i * 4;
            int r = lin >> 7, c = lin & 127;
            float4 v = make_float4(0.f, 0.f, 0.f, 0.f);
            if (row0 + r < n) v = *(const float4*)&A[(size_t)(row0 + r) * F + c];
            *(__half2*)&As[r * SA + c]     = __floats2half2_rn(v.x, v.y);
            *(__half2*)&As[r * SA + c + 2] = __floats2half2_rn(v.z, v.w);
        }
    }
    __syncthreads();

    int w = t >> 5, lane = t & 31;
    int gq = lane >> 2, tq = lane & 3;
    int m0 = w * 16;

    float acc[16][4];
#pragma unroll
    for (int nt = 0; nt < 16; nt++)
#pragma unroll
        for (int c = 0; c < 4; c++) acc[nt][c] = 0.f;

#pragma unroll
    for (int k0 = 0; k0 < F; k0 += 16) {
        uint32_t a0 = *(const uint32_t*)&As[(m0 + gq) * SA + k0 + tq * 2];
        uint32_t a1 = *(const uint32_t*)&As[(m0 + gq + 8) * SA + k0 + tq * 2];
        uint32_t a2 = *(const uint32_t*)&As[(m0 + gq) * SA + k0 + tq * 2 + 8];
        uint32_t a3 = *(const uint32_t*)&As[(m0 + gq + 8) * SA + k0 + tq * 2 + 8];
#pragma unroll
        for (int nt = 0; nt < 16; nt++) {
            uint32_t b0 = *(const uint32_t*)&Wt[(nt * 8 + gq) * SA + k0 + tq * 2];
            uint32_t b1 = *(const uint32_t*)&Wt[(nt * 8 + gq) * SA + k0 + tq * 2 + 8];
            asm volatile(
                "mma.sync.aligned.m16n8k16.row.col.f32.f16.f16.f32 "
                "{%0,%1,%2,%3}, {%4,%5,%6,%7}, {%8,%9}, {%0,%1,%2,%3};"
                : "+f"(acc[nt][0]), "+f"(acc[nt][1]), "+f"(acc[nt][2]), "+f"(acc[nt][3])
                : "r"(a0), "r"(a1), "r"(a2), "r"(a3), "r"(b0), "r"(b1));
        }
    }

    int r1 = row0 + m0 + gq;
    int r2 = r1 + 8;
#pragma unroll
    for (int nt = 0; nt < 16; nt++) {
        int col = nt * 8 + tq * 2;
        if (r1 < n) *(__half2*)&C[(size_t)r1 * F + col] = __floats2half2_rn(acc[nt][0], acc[nt][1]);
        if (r2 < n) *(__half2*)&C[(size_t)r2 * F + col] = __floats2half2_rn(acc[nt][2], acc[nt][3]);
    }
}

// ---------------- CSR gather (warp per node, uint2 per lane, fp32 acc) -----
__device__ __forceinline__ float4 agg_row_scaled(const uint2* __restrict__ gp,
                                                 int node, int lane) {
    uint2 u = __ldg(&gp[(size_t)node * 32 + lane]);   // self loop
    float dn = __ldg(&g_dis[node]);
    float2 f0 = __half22float2(*(const __half2*)&u.x);
    float2 f1 = __half22float2(*(const __half2*)&u.y);
    float4 s = make_float4(f0.x * dn, f0.y * dn, f1.x * dn, f1.y * dn);
    int i = g_rowptr[node];
    int end = g_rowptr[node + 1];
    for (; i + 4 <= end; i += 4) {
        int s0 = __ldg(&g_csr[i + 0]);
        int s1 = __ldg(&g_csr[i + 1]);
        int s2 = __ldg(&g_csr[i + 2]);
        int s3 = __ldg(&g_csr[i + 3]);
        float d0 = __ldg(&g_dis[s0]);
        float d1 = __ldg(&g_dis[s1]);
        float d2 = __ldg(&g_dis[s2]);
        float d3 = __ldg(&g_dis[s3]);
        uint2 u0 = __ldg(&gp[(size_t)s0 * 32 + lane]);
        uint2 u1 = __ldg(&gp[(size_t)s1 * 32 + lane]);
        uint2 u2 = __ldg(&gp[(size_t)s2 * 32 + lane]);
        uint2 u3 = __ldg(&gp[(size_t)s3 * 32 + lane]);
        float2 a0 = __half22float2(*(const __half2*)&u0.x);
        float2 b0 = __half22float2(*(const __half2*)&u0.y);
        float2 a1 = __half22float2(*(const __half2*)&u1.x);
        float2 b1 = __half22float2(*(const __half2*)&u1.y);
        float2 a2 = __half22float2(*(const __half2*)&u2.x);
        float2 b2 = __half22float2(*(const __half2*)&u2.y);
        float2 a3 = __half22float2(*(const __half2*)&u3.x);
        float2 b3 = __half22float2(*(const __half2*)&u3.y);
        s.x += a0.x * d0 + a1.x * d1 + a2.x * d2 + a3.x * d3;
        s.y += a0.y * d0 + a1.y * d1 + a2.y * d2 + a3.y * d3;
        s.z += b0.x * d0 + b1.x * d1 + b2.x * d2 + b3.x * d3;
        s.w += b0.y * d0 + b1.y * d1 + b2.y * d2 + b3.y * d3;
    }
    for (; i < end; i++) {
        int s0 = __ldg(&g_csr[i]);
        float d0 = __ldg(&g_dis[s0]);
        uint2 u0 = __ldg(&gp[(size_t)s0 * 32 + lane]);
        float2 a0 = __half22float2(*(const __half2*)&u0.x);
        float2 b0 = __half22float2(*(const __half2*)&u0.y);
        s.x += a0.x * d0; s.y += a0.y * d0; s.z += b0.x * d0; s.w += b0.y * d0;
    }
    return s;
}

// warp per node: h1 = fp16(relu(dis*sum + b))
__global__ void __launch_bounds__(256) agg1_kernel(const float* __restrict__ b, int n) {
    int w = (blockIdx.x * blockDim.x + threadIdx.x) >> 5;
    int lane = threadIdx.x & 31;
    if (w >= n) return;
    float4 s = agg_row_scaled((const uint2*)g_t1, w, lane);
    float d = g_dis[w];
    float4 bb = __ldg((const float4*)&b[lane * 4]);
    float ox = fmaxf(fmaf(d, s.x, bb.x), 0.f);
    float oy = fmaxf(fmaf(d, s.y, bb.y), 0.f);
    float oz = fmaxf(fmaf(d, s.z, bb.z), 0.f);
    float ow = fmaxf(fmaf(d, s.w, bb.w), 0.f);
    __half2 p0 = __floats2half2_rn(ox, oy);
    __half2 p1 = __floats2half2_rn(oz, ow);
    uint2 st;
    st.x = *(uint32_t*)&p0;
    st.y = *(uint32_t*)&p1;
    ((uint2*)g_h1)[(size_t)w * 32 + lane] = st;
}

// warp per node: o = relu(dis*sum + b); mean-pool scatter
__global__ void __launch_bounds__(256) agg2_kernel(
    const void* __restrict__ batch, const float* __restrict__ b,
    float* __restrict__ out, int n)
{
    int w = (blockIdx.x * blockDim.x + threadIdx.x) >> 5;
    int lane = threadIdx.x & 31;
    if (w >= n) return;
    float4 s = agg_row_scaled((const uint2*)g_t2, w, lane);
    float d = g_dis[w];
    float4 bb = __ldg((const float4*)&b[lane * 4]);
    float4 o;
    o.x = fmaxf(fmaf(d, s.x, bb.x), 0.f);
    o.y = fmaxf(fmaf(d, s.y, bb.y), 0.f);
    o.z = fmaxf(fmaf(d, s.z, bb.z), 0.f);
    o.w = fmaxf(fmaf(d, s.w, bb.w), 0.f);
    long long gid = load_idx(batch, w, g_b64);
    float* p = &out[(size_t)gid * F + lane * 4];
    asm volatile("red.global.add.v4.f32 [%0], {%1,%2,%3,%4};"
                 :: "l"(p), "f"(o.x), "f"(o.y), "f"(o.z), "f"(o.w) : "memory");
    if (lane == 0) atomicAdd(&g_counts[gid], 1);
}

__global__ void div_kernel(float* __restrict__ out, int gtot) {
    int i = blockIdx.x * blockDim.x + threadIdx.x;
    if (i >= gtot * F) return;
    int gidx = i >> 7;
    float cnt = (float)max(g_counts[gidx], 1);
    out[i] = out[i] / cnt;
}

// ---------------- launch ----------------
extern "C" void kernel_launch(void* const* d_in, const int* in_sizes, int n_in,
                              void* d_out, int out_size) {
    const float* x    = (const float*)d_in[0];
    const void*  edge = d_in[1];
    const void*  batch= d_in[2];
    const float* W1   = (const float*)d_in[3];
    const float* b1   = (const float*)d_in[4];
    const float* W2   = (const float*)d_in[5];
    const float* b2   = (const float*)d_in[6];
    float* out = (float*)d_out;

    int N = in_sizes[0] / F;
    int E = in_sizes[1] / 2;
    int G = out_size / F;

    void *p_t1, *p_h1, *p_t2;
    cudaGetSymbolAddress(&p_t1, g_t1);
    cudaGetSymbolAddress(&p_h1, g_h1);
    cudaGetSymbolAddress(&p_t2, g_t2);

    const int SMEM = 2 * 128 * SA * (int)sizeof(__half);   // 69632 bytes
    cudaFuncSetAttribute(gemm_mma_kernel<false>, cudaFuncAttributeMaxDynamicSharedMemorySize, SMEM);
    cudaFuncSetAttribute(gemm_mma_kernel<true>,  cudaFuncAttributeMaxDynamicSharedMemorySize, SMEM);

    const int TB = 256;
    int gemm_grid = (N + 127) / 128;
    int agg_grid = (N + 7) / 8;
    int nblk = (N + TILE - 1) / TILE;
    int epairs = (E + 1) / 2;

    // fork: gemm1 overlaps the whole preproc chain (independent of it)
    cudaStream_t s1;
    cudaStreamCreateWithFlags(&s1, cudaStreamNonBlocking);
    cudaEvent_t eA, eB;
    cudaEventCreateWithFlags(&eA, cudaEventDisableTiming);
    cudaEventCreateWithFlags(&eB, cudaEventDisableTiming);

    cudaEventRecord(eA, 0);
    cudaStreamWaitEvent(s1, eA, 0);
    gemm_mma_kernel<false><<<gemm_grid, 256, SMEM, s1>>>(x, W1, (__half*)p_t1, N);
    cudaEventRecord(eB, s1);

    // main stream: setup -> deg(+rank) -> scan(+dis) -> fill (atomic-free)
    setup_kernel<<<2 + 192, TB>>>((const int*)edge, (const int*)batch, 2048, out, G * F, N);
    deg_kernel<<<(epairs + TB - 1) / TB, TB>>>(edge, E);
    scan_kernel<<<nblk, TILE>>>(N);
    fill_kernel<<<(epairs + TB - 1) / TB, TB>>>(edge, E);

    // join, then the serial tail
    cudaStreamWaitEvent(0, eB, 0);
    agg1_kernel<<<agg_grid, TB>>>(b1, N);
    gemm_mma_kernel<true><<<gemm_grid, 256, SMEM>>>(p_h1, W2, (__half*)p_t2, N);
    agg2_kernel<<<agg_grid, TB>>>(batch, b2, out, N);
    div_kernel<<<(G * F + TB - 1) / TB, TB>>>(out, G);

    cudaEventDestroy(eA);
    cudaEventDestroy(eB);
    cudaStreamDestroy(s1);
}

// round 9
// speedup vs baseline: 1.0688x; 1.0688x over previous
#include <cuda_runtime.h>
#include <cuda_fp16.h>
#include <cuda_bf16.h>
#include <stdint.h>

// ---------------- static scratch (no allocation allowed) ----------------
#define N_MAX 100352          // >= N=100000
#define E_MAX 1700000         // >= E=1600000
#define F 128                 // feature dim
#define SA 136                // padded smem row stride (halves)

__device__ __align__(16) static __half g_t1[(size_t)N_MAX * F];  // (x@W1)*dis (fp16)
__device__ __align__(16) static __half g_h1[(size_t)N_MAX * F];  // relu layer-1 out (fp16)
__device__ __align__(16) static __half g_t2[(size_t)N_MAX * F];  // (h1@W2)*dis (fp16)
__device__ __align__(16) static float g_dis[N_MAX];
__device__ static int   g_degc[N_MAX];
__device__ static int   g_rowptr[N_MAX + 4];
__device__ static int   g_rank[E_MAX];
__device__ static int   g_csr[E_MAX];
__device__ static int   g_part[256];
__device__ static int   g_counts[1024];
__device__ static int   g_e64;
__device__ static int   g_b64;

// ---------------- kernel 1: dtype detect + zero everything ----------------
__global__ void setup_kernel(const int* __restrict__ e, const int* __restrict__ b,
                             int nwords, float* __restrict__ out, int outw, int n) {
    if (blockIdx.x < 2) {
        __shared__ int any;
        if (threadIdx.x == 0) any = 0;
        __syncthreads();
        const int* a = (blockIdx.x == 0) ? e : b;
        int local = 0;
        for (int i = 1 + 2 * (int)threadIdx.x; i < nwords; i += 2 * (int)blockDim.x)
            local |= a[i];
        if (local) atomicOr(&any, 1);
        __syncthreads();
        if (threadIdx.x == 0) {
            int is64 = (any == 0) ? 1 : 0;
            if (blockIdx.x == 0) g_e64 = is64; else g_b64 = is64;
        }
        if (blockIdx.x == 1) {
            for (int i = threadIdx.x; i < 1024; i += blockDim.x) g_counts[i] = 0;
        }
        return;
    }
    int nb = gridDim.x - 2;
    long long idx = (long long)(blockIdx.x - 2) * blockDim.x + threadIdx.x;
    long long stride = (long long)nb * blockDim.x;
    for (long long i = idx; i < n; i += stride) g_degc[i] = 0;
    for (long long i = idx; i < outw; i += stride) out[i] = 0.f;
}

__device__ __forceinline__ long long load_idx(const void* p, long long i, int is64) {
    if (is64) return ((const long long*)p)[i];
    return (long long)((const int*)p)[i];
}

// load edge indices [i, i+1] (i even) as a pair
__device__ __forceinline__ void load_pair(const void* p, long long i, int is64,
                                          int& v0, int& v1) {
    if (is64) {
        longlong2 v = ((const longlong2*)p)[i >> 1];
        v0 = (int)v.x; v1 = (int)v.y;
    } else {
        int2 v = ((const int2*)p)[i >> 1];
        v0 = v.x; v1 = v.y;
    }
}

// ---------------- kernel 2: degree histogram + per-edge rank ----------------
__global__ void deg_kernel(const void* __restrict__ edge, int E) {
    int t = blockIdx.x * blockDim.x + threadIdx.x;
    int e0 = 2 * t;
    if (e0 >= E) return;
    int is64 = g_e64;
    if (e0 + 1 < E) {
        int d0, d1;
        load_pair(edge, (long long)E + e0, is64, d0, d1);
        g_rank[e0]     = atomicAdd(&g_degc[d0], 1);
        g_rank[e0 + 1] = atomicAdd(&g_degc[d1], 1);
    } else {
        int d0 = (int)load_idx(edge, (long long)E + e0, is64);
        g_rank[e0] = atomicAdd(&g_degc[d0], 1);
    }
}

// ---------------- kernels 3-5: 3-level scan (+dis fused) ----------------
__global__ void scan1_kernel(int n) {                 // block = 1024
    __shared__ int sh[1024];
    int t = threadIdx.x;
    int i = blockIdx.x * 1024 + t;
    int v = (i < n) ? g_degc[i] : 0;
    if (i < n) g_dis[i] = rsqrtf((float)(v + 1));     // +1 self loop
    sh[t] = v;
    __syncthreads();
    for (int off = 1; off < 1024; off <<= 1) {
        int tmp = (t >= off) ? sh[t - off] : 0;
        __syncthreads();
        sh[t] += tmp;
        __syncthreads();
    }
    if (i < n) g_rowptr[i] = sh[t] - v;
    if (t == 1023) g_part[blockIdx.x] = sh[1023];
}

__global__ void scan2_kernel(int nblk) {              // 1 block of 256
    __shared__ int sh[256];
    int t = threadIdx.x;
    int v = (t < nblk) ? g_part[t] : 0;
    sh[t] = v;
    __syncthreads();
    for (int off = 1; off < 256; off <<= 1) {
        int tmp = (t >= off) ? sh[t - off] : 0;
        __syncthreads();
        sh[t] += tmp;
        __syncthreads();
    }
    g_part[t] = sh[t] - v;
}

__global__ void scan3_kernel(int n) {                 // block = 1024
    int i = blockIdx.x * 1024 + threadIdx.x;
    if (i >= n) return;
    int r = g_rowptr[i] + g_part[blockIdx.x];
    g_rowptr[i] = r;
    if (i == n - 1) g_rowptr[n] = r + g_degc[i];
}

// ---------------- kernel 6: CSR fill, atomic-free ----------------
__global__ void fill_kernel(const void* __restrict__ edge, int E) {
    int t = blockIdx.x * blockDim.x + threadIdx.x;
    int e0 = 2 * t;
    if (e0 >= E) return;
    int is64 = g_e64;
    if (e0 + 1 < E) {
        int s0, s1, d0, d1;
        load_pair(edge, (long long)e0, is64, s0, s1);
        load_pair(edge, (long long)E + e0, is64, d0, d1);
        int2 rk = *(const int2*)&g_rank[e0];
        g_csr[g_rowptr[d0] + rk.x] = s0;
        g_csr[g_rowptr[d1] + rk.y] = s1;
    } else {
        int s0 = (int)load_idx(edge, (long long)e0, is64);
        int d0 = (int)load_idx(edge, (long long)E + e0, is64);
        g_csr[g_rowptr[d0] + g_rank[e0]] = s0;
    }
}

// ---------------- tensor-core GEMM: C = fp16((A @ W) * dis[row]) -----------
template<bool A_IS_HALF>
__global__ void __launch_bounds__(256) gemm_mma_kernel(
    const void* __restrict__ Aptr, const float* __restrict__ W,
    __half* __restrict__ C, int n)
{
    extern __shared__ __half sh[];
    __half* As = sh;                 // [128][SA]
    __half* Wt = sh + 128 * SA;      // [128][SA] transposed

    int t = threadIdx.x;
    int row0 = blockIdx.x * 128;

    for (int i = t; i < F * F; i += 256) {
        int k = i >> 7, nn = i & 127;
        Wt[nn * SA + k] = __float2half(__ldg(&W[i]));
    }

    if (A_IS_HALF) {
        const __half* A = (const __half*)Aptr;
        for (int i = t; i < 128 * F / 8; i += 256) {
            int lin = i * 8;
            int r = lin >> 7, c = lin & 127;
            uint4 v = make_uint4(0u, 0u, 0u, 0u);
            if (row0 + r < n) v = *(const uint4*)&A[(size_t)(row0 + r) * F + c];
            *(uint4*)&As[r * SA + c] = v;
        }
    } else {
        const float* A = (const float*)Aptr;
        for (int i = t; i < 128 * F / 4; i += 256) {
            int lin = i * 4;
            int r = lin >> 7, c = lin & 127;
            float4 v = make_float4(0.f, 0.f, 0.f, 0.f);
            if (row0 + r < n) v = *(const float4*)&A[(size_t)(row0 + r) * F + c];
            *(__half2*)&As[r * SA + c]     = __floats2half2_rn(v.x, v.y);
            *(__half2*)&As[r * SA + c + 2] = __floats2half2_rn(v.z, v.w);
        }
    }
    __syncthreads();

    int w = t >> 5, lane = t & 31;
    int gq = lane >> 2, tq = lane & 3;
    int m0 = w * 16;

    float acc[16][4];
#pragma unroll
    for (int nt = 0; nt < 16; nt++)
#pragma unroll
        for (int c = 0; c < 4; c++) acc[nt][c] = 0.f;

#pragma unroll
    for (int k0 = 0; k0 < F; k0 += 16) {
        uint32_t a0 = *(const uint32_t*)&As[(m0 + gq) * SA + k0 + tq * 2];
        uint32_t a1 = *(const uint32_t*)&As[(m0 + gq + 8) * SA + k0 + tq * 2];
        uint32_t a2 = *(const uint32_t*)&As[(m0 + gq) * SA + k0 + tq * 2 + 8];
        uint32_t a3 = *(const uint32_t*)&As[(m0 + gq + 8) * SA + k0 + tq * 2 + 8];
#pragma unroll
        for (int nt = 0; nt < 16; nt++) {
            uint32_t b0 = *(const uint32_t*)&Wt[(nt * 8 + gq) * SA + k0 + tq * 2];
            uint32_t b1 = *(const uint32_t*)&Wt[(nt * 8 + gq) * SA + k0 + tq * 2 + 8];
            asm volatile(
                "mma.sync.aligned.m16n8k16.row.col.f32.f16.f16.f32 "
                "{%0,%1,%2,%3}, {%4,%5,%6,%7}, {%8,%9}, {%0,%1,%2,%3};"
                : "+f"(acc[nt][0]), "+f"(acc[nt][1]), "+f"(acc[nt][2]), "+f"(acc[nt][3])
                : "r"(a0), "r"(a1), "r"(a2), "r"(a3), "r"(b0), "r"(b1));
        }
    }

    int r1 = row0 + m0 + gq;
    int r2 = r1 + 8;
    float d1 = (r1 < n) ? g_dis[r1] : 0.f;
    float d2 = (r2 < n) ? g_dis[r2] : 0.f;
#pragma unroll
    for (int nt = 0; nt < 16; nt++) {
        int col = nt * 8 + tq * 2;
        if (r1 < n) *(__half2*)&C[(size_t)r1 * F + col] = __floats2half2_rn(acc[nt][0] * d1, acc[nt][1] * d1);
        if (r2 < n) *(__half2*)&C[(size_t)r2 * F + col] = __floats2half2_rn(acc[nt][2] * d2, acc[nt][3] * d2);
    }
}

// ---------------- CSR gather (warp per node, pre-scaled features) ----------
__device__ __forceinline__ float4 agg_row(const uint2* __restrict__ gp,
                                          int node, int lane) {
    uint2 u = __ldg(&gp[(size_t)node * 32 + lane]);   // self loop (pre-scaled)
    float2 f0 = __half22float2(*(const __half2*)&u.x);
    float2 f1 = __half22float2(*(const __half2*)&u.y);
    float4 s = make_float4(f0.x, f0.y, f1.x, f1.y);
    int i = g_rowptr[node];
    int end = g_rowptr[node + 1];
    for (; i + 4 <= end; i += 4) {
        int s0 = __ldg(&g_csr[i + 0]);
        int s1 = __ldg(&g_csr[i + 1]);
        int s2 = __ldg(&g_csr[i + 2]);
        int s3 = __ldg(&g_csr[i + 3]);
        uint2 u0 = __ldg(&gp[(size_t)s0 * 32 + lane]);
        uint2 u1 = __ldg(&gp[(size_t)s1 * 32 + lane]);
        uint2 u2 = __ldg(&gp[(size_t)s2 * 32 + lane]);
        uint2 u3 = __ldg(&gp[(size_t)s3 * 32 + lane]);
        float2 a0 = __half22float2(*(const __half2*)&u0.x);
        float2 b0 = __half22float2(*(const __half2*)&u0.y);
        float2 a1 = __half22float2(*(const __half2*)&u1.x);
        float2 b1 = __half22float2(*(const __half2*)&u1.y);
        float2 a2 = __half22float2(*(const __half2*)&u2.x);
        float2 b2 = __half22float2(*(const __half2*)&u2.y);
        float2 a3 = __half22float2(*(const __half2*)&u3.x);
        float2 b3 = __half22float2(*(const __half2*)&u3.y);
        s.x += a0.x + a1.x + a2.x + a3.x;
        s.y += a0.y + a1.y + a2.y + a3.y;
        s.z += b0.x + b1.x + b2.x + b3.x;
        s.w += b0.y + b1.y + b2.y + b3.y;
    }
    for (; i < end; i++) {
        int s0 = __ldg(&g_csr[i]);
        uint2 u0 = __ldg(&gp[(size_t)s0 * 32 + lane]);
        float2 a0 = __half22float2(*(const __half2*)&u0.x);
        float2 b0 = __half22float2(*(const __half2*)&u0.y);
        s.x += a0.x; s.y += a0.y; s.z += b0.x; s.w += b0.y;
    }
    return s;
}

// kernel 8: h1 = fp16(relu(dis*sum + b))
__global__ void __launch_bounds__(256) agg1_kernel(const float* __restrict__ b, int n) {
    int w = (blockIdx.x * blockDim.x + threadIdx.x) >> 5;
    int lane = threadIdx.x & 31;
    if (w >= n) return;
    float4 s = agg_row((const uint2*)g_t1, w, lane);
    float d = g_dis[w];
    float4 bb = __ldg((const float4*)&b[lane * 4]);
    float ox = fmaxf(fmaf(d, s.x, bb.x), 0.f);
    float oy = fmaxf(fmaf(d, s.y, bb.y), 0.f);
    float oz = fmaxf(fmaf(d, s.z, bb.z), 0.f);
    float ow = fmaxf(fmaf(d, s.w, bb.w), 0.f);
    __half2 p0 = __floats2half2_rn(ox, oy);
    __half2 p1 = __floats2half2_rn(oz, ow);
    uint2 st;
    st.x = *(uint32_t*)&p0;
    st.y = *(uint32_t*)&p1;
    ((uint2*)g_h1)[(size_t)w * 32 + lane] = st;
}

// kernel 10: o = relu(dis*sum + b); mean-pool scatter
__global__ void __launch_bounds__(256) agg2_kernel(
    const void* __restrict__ batch, const float* __restrict__ b,
    float* __restrict__ out, int n)
{
    int w = (blockIdx.x * blockDim.x + threadIdx.x) >> 5;
    int lane = threadIdx.x & 31;
    if (w >= n) return;
    float4 s = agg_row((const uint2*)g_t2, w, lane);
    float d = g_dis[w];
    float4 bb = __ldg((const float4*)&b[lane * 4]);
    float4 o;
    o.x = fmaxf(fmaf(d, s.x, bb.x), 0.f);
    o.y = fmaxf(fmaf(d, s.y, bb.y), 0.f);
    o.z = fmaxf(fmaf(d, s.z, bb.z), 0.f);
    o.w = fmaxf(fmaf(d, s.w, bb.w), 0.f);
    long long gid = load_idx(batch, w, g_b64);
    float* p = &out[(size_t)gid * F + lane * 4];
    asm volatile("red.global.add.v4.f32 [%0], {%1,%2,%3,%4};"
                 :: "l"(p), "f"(o.x), "f"(o.y), "f"(o.z), "f"(o.w) : "memory");
    if (lane == 0) atomicAdd(&g_counts[gid], 1);
}

// kernel 11: divide by counts
__global__ void div_kernel(float* __restrict__ out, int gtot) {
    int i = blockIdx.x * blockDim.x + threadIdx.x;
    if (i >= gtot * F) return;
    int gidx = i >> 7;
    float cnt = (float)max(g_counts[gidx], 1);
    out[i] = out[i] / cnt;
}

// ---------------- launch ----------------
extern "C" void kernel_launch(void* const* d_in, const int* in_sizes, int n_in,
                              void* d_out, int out_size) {
    const float* x    = (const float*)d_in[0];
    const void*  edge = d_in[1];
    const void*  batch= d_in[2];
    const float* W1   = (const float*)d_in[3];
    const float* b1   = (const float*)d_in[4];
    const float* W2   = (const float*)d_in[5];
    const float* b2   = (const float*)d_in[6];
    float* out = (float*)d_out;

    int N = in_sizes[0] / F;
    int E = in_sizes[1] / 2;
    int G = out_size / F;

    void *p_t1, *p_h1, *p_t2;
    cudaGetSymbolAddress(&p_t1, g_t1);
    cudaGetSymbolAddress(&p_h1, g_h1);
    cudaGetSymbolAddress(&p_t2, g_t2);

    const int SMEM = 2 * 128 * SA * (int)sizeof(__half);   // 69632 bytes
    cudaFuncSetAttribute(gemm_mma_kernel<false>, cudaFuncAttributeMaxDynamicSharedMemorySize, SMEM);
    cudaFuncSetAttribute(gemm_mma_kernel<true>,  cudaFuncAttributeMaxDynamicSharedMemorySize, SMEM);

    const int TB = 256;
    int gemm_grid = (N + 127) / 128;
    int agg_grid = (N + 7) / 8;
    int nblk = (N + 1023) / 1024;
    int epairs = (E + 1) / 2;

    // serial pipeline, 11 launches
    setup_kernel<<<2 + 192, TB>>>((const int*)edge, (const int*)batch, 2048, out, G * F, N);
    deg_kernel<<<(epairs + TB - 1) / TB, TB>>>(edge, E);
    scan1_kernel<<<nblk, 1024>>>(N);
    scan2_kernel<<<1, 256>>>(nblk);
    scan3_kernel<<<nblk, 1024>>>(N);
    fill_kernel<<<(epairs + TB - 1) / TB, TB>>>(edge, E);

    gemm_mma_kernel<false><<<gemm_grid, 256, SMEM>>>(x, W1, (__half*)p_t1, N);
    agg1_kernel<<<agg_grid, TB>>>(b1, N);
    gemm_mma_kernel<true><<<gemm_grid, 256, SMEM>>>(p_h1, W2, (__half*)p_t2, N);
    agg2_kernel<<<agg_grid, TB>>>(batch, b2, out, N);
    div_kernel<<<(G * F + TB - 1) / TB, TB>>>(out, G);
}